// round 8
// baseline (speedup 1.0000x reference)
#include <cuda_runtime.h>
#include <math.h>

#define NCOL 22
#define NEMB 12
#define D    64
#define B    2048
#define NPAIR 253           // 22 diag + 231 upper pairs
#define NE2  (NEMB*NEMB)    // 144
#define SZ   (NCOL*NCOL*2*D)

// ---------------- scratch (device globals; no allocation allowed) ------------
__device__ float  g_T[NCOL * NEMB * D];        // f(tables), 66 KB
__device__ float  g_colsq[NCOL];               // per-col sum of squared norms
__device__ float  g_L[NCOL * 2 * D];           // folded linear weights [i][o][d]
__device__ float2 g_S[NPAIR * NE2];            // pairwise lookup table, 291 KB

// p -> (i,j) upper-triangular-incl-diag enumeration
__device__ __forceinline__ void pair_ij(int p, int& i, int& j) {
    int ii = 0, rem = p;
    while (rem >= NCOL - ii) { rem -= NCOL - ii; ii++; }
    i = ii; j = ii + rem;
}

// fast tanh: one MUFU.EX2, safe for any x
__device__ __forceinline__ float tanh_fast(float x) {
    float e = __expf(-2.0f * fabsf(x));
    float t = __fdividef(1.0f - e, 1.0f + e);
    return copysignf(t, x);
}

// ---------------- k_pre: embed (blocks 0..21) + folded linear L (22..65) -----
__global__ void __launch_bounds__(256, 4)
k_pre(const float* __restrict__ tables, const int* __restrict__ features,
      const float* __restrict__ w1, const float* __restrict__ b1,
      const float* __restrict__ w2, const float* __restrict__ b2,
      const float* __restrict__ Wops, const float* __restrict__ Wcat,
      const float* __restrict__ aw) {
    int bid = blockIdx.x, t = threadIdx.x;

    if (bid < NCOL) {
        // ---- embed: T[i,e,d] = f(tables), n2 per e, colsq per column ----
        int i = bid;
        __shared__ float s_warp[24];
        __shared__ float s_n2[NEMB];
#pragma unroll
        for (int c = 0; c < 3; c++) {                 // 3*256 = 768 = NEMB*D
            int idx = c * 256 + t;
            float x = tables[i * NEMB * D + idx];
            float acc = b2[0];
#pragma unroll
            for (int h = 0; h < 8; h++) acc += w2[h] * tanh_fast(x * w1[h] + b1[h]);
            g_T[i * NEMB * D + idx] = acc;
            float sq = x * x;
#pragma unroll
            for (int o = 16; o; o >>= 1) sq += __shfl_xor_sync(0xffffffffu, sq, o);
            if ((t & 31) == 0) s_warp[idx >> 5] = sq;   // 24 half-e partials
            __syncthreads();
        }
        if (t < NEMB) s_n2[t] = s_warp[2 * t] + s_warp[2 * t + 1];
        __syncthreads();
        float sum = 0.f;
        for (int b = t; b < B; b += 256)
            sum += s_n2[features[i * B + b]];
#pragma unroll
        for (int o = 16; o; o >>= 1) sum += __shfl_xor_sync(0xffffffffu, sum, o);
        if ((t & 31) == 0) s_warp[t >> 5] = sum;
        __syncthreads();
        if (t == 0) {
            float v = 0.f;
            for (int k = 0; k < 8; k++) v += s_warp[k];
            g_colsq[i] = v;
        }
    } else {
        // ---- L[i,o,d]: out_plus + out_cat + (t_i+t_j)/2 halves of max/min ----
        int lb = bid - NCOL;
        int i = lb >> 1, o = lb & 1;
        int d = t & 63, g = t >> 6;                    // 4 j-slices
        float sp = 0.f, smx = 0.f, smn = 0.f, sct = 0.f;
        for (int j = g; j < NCOL; j += 4) {
            int ij = ((i * NCOL + j) * 2 + o) * D + d;
            int ji = ((j * NCOL + i) * 2 + o) * D + d;
            sp  += Wops[ij]          + Wops[ji];
            smx += Wops[2 * SZ + ij] + Wops[2 * SZ + ji];
            smn += Wops[3 * SZ + ij] + Wops[3 * SZ + ji];
            sct += Wcat[((i * NCOL + j) * 2 + o) * (2 * D) + d]        // Wc1 row-sum
                 + Wcat[((j * NCOL + i) * 2 + o) * (2 * D) + D + d];   // Wc2 col-sum
        }
        __shared__ float4 s_red[4][64];
        s_red[g][d] = make_float4(sp, smx, smn, sct);
        __syncthreads();
        if (t < 64) {
            float4 a = s_red[0][t], b = s_red[1][t], c = s_red[2][t], e = s_red[3][t];
            g_L[lb * D + t] = aw[0] * (a.x + b.x + c.x + e.x)
                            + aw[4] * (a.w + b.w + c.w + e.w)
                            + 0.5f * (aw[2] * (a.y + b.y + c.y + e.y)
                                    + aw[3] * (a.z + b.z + c.z + e.z));
        }
    }
}

// ---------------- k_S: symmetrize weights inline + tabulate per (pair,e1,e2) --
// S[p][e1][e2] = { sum_d wq0*Ti*Tj + wd0*|Ti-Tj| , same with wq1/wd1 }
// Diagonal pairs fold the linear term into e1==e2 entries (only ones read).
__global__ void __launch_bounds__(256, 6)
k_S(const float* __restrict__ Wops, const float* __restrict__ aw) {
    int p = blockIdx.x;
    int i, j; pair_ij(p, i, j);
    int t = threadIdx.x;
    bool diag = (i == j);

    __shared__ float  sTi[NEMB * D];
    __shared__ float  sTj[NEMB * D];
    __shared__ float  sWraw[12][D];      // 12 raw weight rows
    __shared__ float4 sW[D];             // {wq0,wq1,wd0,wd1}
    __shared__ float  sL[2 * D];

    // T tiles
    for (int idx = t; idx < NEMB * D; idx += 256) {
        sTi[idx] = g_T[i * NEMB * D + idx];
        sTj[idx] = g_T[j * NEMB * D + idx];
    }
    // 12 raw weight rows: op in {Wm=1, Wmax=2, Wmin=3} x dir{ij,ji} x o{0,1}
    // FIX R7: strided loop (256 threads must cover 12*64=768 elements)
    {
        int rij = (i * NCOL + j) * 2, rji = (j * NCOL + i) * 2;
        for (int idx = t; idx < 12 * D; idx += 256) {
            int r = idx >> 6, d = idx & 63;
            int op = 1 + (r >> 2);              // r/4: 0->Wm,1->Wmax,2->Wmin
            int sub = r & 3;                    // dir*2 + o
            int row = (sub < 2) ? rij : rji;
            int o   = sub & 1;
            sWraw[r][d] = Wops[op * SZ + (row + o) * D + d];
        }
    }
    if (diag)
        for (int idx = t; idx < 2 * D; idx += 256) sL[idx] = g_L[i * 2 * D + idx];
    __syncthreads();

    // symmetrize: 256 threads = 4 components x 64 d
    if (t < 4 * D) {
        int comp = t >> 6, d = t & 63;
        float aw1 = aw[1], aw2 = aw[2], aw3 = aw[3];
        float v;
        if (comp < 2) {          // wq for o = comp
            v = diag ? aw1 * sWraw[comp][d]
                     : aw1 * (sWraw[comp][d] + sWraw[2 + comp][d]);
        } else if (diag) {
            v = 0.f;             // wd vanishes on diagonal
        } else {
            int o = comp - 2;
            v = 0.5f * (aw2 * (sWraw[4 + o][d] + sWraw[6 + o][d])
                      - aw3 * (sWraw[8 + o][d] + sWraw[10 + o][d]));
        }
        float* f = (float*)&sW[d];
        f[comp] = v;
    }
    __syncthreads();

    if (t < NE2) {
        int e1 = t / NEMB, e2 = t % NEMB;
        bool dl = diag && (e1 == e2);
        float s0 = 0.f, s1 = 0.f, l0 = 0.f, l1 = 0.f;
#pragma unroll 4
        for (int d = 0; d < D; d++) {
            float4 w = sW[d];
            float ti = sTi[e1 * D + d], tj = sTj[e2 * D + d];
            float m = ti * tj;
            float a = fabsf(ti - tj);
            s0 = fmaf(w.x, m, fmaf(w.z, a, s0));
            s1 = fmaf(w.y, m, fmaf(w.w, a, s1));
            if (dl) { l0 = fmaf(ti, sL[d], l0); l1 = fmaf(ti, sL[D + d], l1); }
        }
        if (dl) { s0 += l0; s1 += l1; }
        g_S[p * NE2 + t] = make_float2(s0, s1);
    }
}

// ---------------- k_main: batch-per-lane gathers (warp-uniform pair) ---------
// Block: 16 batches, 8 warps. Warp w owns pair chunk [w*32, w*32+32).
// Lane = (subchunk s, batch bl): 16 lanes share one pair -> gather instruction
// touches <=2 S-slabs instead of 32.
__global__ void __launch_bounds__(256, 8)
k_main(const int* __restrict__ features, float* __restrict__ out, int out_size) {
    __shared__ int   s_feat[NCOL][16];
    __shared__ float s_red[8][16][2];
    int t = threadIdx.x;
    int b0 = blockIdx.x * 16;

    for (int idx = t; idx < NCOL * 16; idx += 256)
        s_feat[idx >> 4][idx & 15] = features[(idx >> 4) * B + b0 + (idx & 15)];
    __syncthreads();

    int w = t >> 5, l = t & 31;
    int bl = l & 15, s = l >> 4;
    int pc = w * 32 + s * 16;
    int i, j; pair_ij(pc, i, j);

    float a0 = 0.f, a1 = 0.f;
#pragma unroll
    for (int k = 0; k < 16; k++) {
        int p = pc + k;
        if (p < NPAIR) {
            int e1 = s_feat[i][bl], e2 = s_feat[j][bl];
            float2 v = __ldg(&g_S[p * NE2 + e1 * NEMB + e2]);
            a0 += v.x; a1 += v.y;
            j++; if (j == NCOL) { i++; j = i; }
        }
    }
    a0 += __shfl_xor_sync(0xffffffffu, a0, 16);
    a1 += __shfl_xor_sync(0xffffffffu, a1, 16);
    if (s == 0) { s_red[w][bl][0] = a0; s_red[w][bl][1] = a1; }
    __syncthreads();
    if (t < 16) {
        float r0 = 0.f, r1 = 0.f;
#pragma unroll
        for (int ww = 0; ww < 8; ww++) { r0 += s_red[ww][t][0]; r1 += s_red[ww][t][1]; }
        int b = b0 + t;
        out[b * 2] = r0; out[b * 2 + 1] = r1;
    }

    // regularizer scalar (colsq ready from k_pre)
    if (blockIdx.x == 0 && t >= 32 && t < 64 && out_size > 2 * B) {
        int ll = t - 32;
        float v = (ll < NCOL) ? sqrtf(g_colsq[ll]) : 0.f;
#pragma unroll
        for (int o = 16; o; o >>= 1) v += __shfl_xor_sync(0xffffffffu, v, o);
        if (ll == 0) out[2 * B] = 0.001f * (2.0f * NCOL) * v;
    }
}

// ---------------- launch -----------------------------------------------------
extern "C" void kernel_launch(void* const* d_in, const int* in_sizes, int n_in,
                              void* d_out, int out_size) {
    const int*   features = (const int*)  d_in[0];
    const float* tables   = (const float*)d_in[1];
    const float* w1       = (const float*)d_in[2];
    const float* b1       = (const float*)d_in[3];
    const float* w2       = (const float*)d_in[4];
    const float* b2       = (const float*)d_in[5];
    const float* Wops     = (const float*)d_in[6];
    const float* Wcat     = (const float*)d_in[7];
    const float* aw       = (const float*)d_in[8];
    float* out = (float*)d_out;

    k_pre  <<<NCOL * 3, 256>>>(tables, features, w1, b1, w2, b2, Wops, Wcat, aw);
    k_S    <<<NPAIR, 256>>>(Wops, aw);
    k_main <<<B / 16, 256>>>(features, out, out_size);
}

// round 9
// speedup vs baseline: 1.2736x; 1.2736x over previous
#include <cuda_runtime.h>
#include <math.h>

#define NCOL 22
#define NEMB 12
#define D    64
#define B    2048
#define NPAIR 253           // 22 diag + 231 upper pairs
#define NE2  (NEMB*NEMB)    // 144
#define SZ   (NCOL*NCOL*2*D)

// ---------------- scratch (device globals; no allocation allowed) ------------
__device__ float  g_T[NCOL * NEMB * D];        // f(tables), 66 KB
__device__ float  g_colsq[NCOL];               // per-col sum of squared norms
__device__ float  g_L[NCOL * 2 * D];           // folded linear weights [i][o][d]
__device__ float2 g_S[NPAIR * NE2];            // pairwise lookup table, 291 KB

// p -> (i,j) upper-triangular-incl-diag enumeration
__device__ __forceinline__ void pair_ij(int p, int& i, int& j) {
    int ii = 0, rem = p;
    while (rem >= NCOL - ii) { rem -= NCOL - ii; ii++; }
    i = ii; j = ii + rem;
}

// fast tanh: one MUFU.EX2, safe for any x
__device__ __forceinline__ float tanh_fast(float x) {
    float e = __expf(-2.0f * fabsf(x));
    float t = __fdividef(1.0f - e, 1.0f + e);
    return copysignf(t, x);
}

// ---------------- k_pre: embed (blocks 0..21) + folded linear L (22..65) -----
// 768 threads: embed = 1 table element per thread (no serial passes);
// L = 12 j-slices (<=2 j per thread, ~16 loads in 2 dependency rounds).
__global__ void __launch_bounds__(768, 1)
k_pre(const float* __restrict__ tables, const int* __restrict__ features,
      const float* __restrict__ w1, const float* __restrict__ b1,
      const float* __restrict__ w2, const float* __restrict__ b2,
      const float* __restrict__ Wops, const float* __restrict__ Wcat,
      const float* __restrict__ aw) {
    int bid = blockIdx.x, t = threadIdx.x;

    if (bid < NCOL) {
        // ---- embed: T[i,e,d] = f(tables), n2 per e, colsq per column ----
        int i = bid;
        __shared__ float s_warp[24];
        __shared__ float s_n2[NEMB];
        float x = tables[i * NEMB * D + t];
        float acc = b2[0];
#pragma unroll
        for (int h = 0; h < 8; h++) acc += w2[h] * tanh_fast(x * w1[h] + b1[h]);
        g_T[i * NEMB * D + t] = acc;

        float sq = x * x;
#pragma unroll
        for (int o = 16; o; o >>= 1) sq += __shfl_xor_sync(0xffffffffu, sq, o);
        if ((t & 31) == 0) s_warp[t >> 5] = sq;        // 24 half-e partials
        __syncthreads();
        if (t < NEMB) s_n2[t] = s_warp[2 * t] + s_warp[2 * t + 1];
        __syncthreads();

        float sum = 0.f;
        for (int b = t; b < B; b += 768)
            sum += s_n2[features[i * B + b]];
#pragma unroll
        for (int o = 16; o; o >>= 1) sum += __shfl_xor_sync(0xffffffffu, sum, o);
        if ((t & 31) == 0) s_warp[t >> 5] = sum;
        __syncthreads();
        if (t < 32) {
            float v = (t < 24) ? s_warp[t] : 0.f;
#pragma unroll
            for (int o = 16; o; o >>= 1) v += __shfl_xor_sync(0xffffffffu, v, o);
            if (t == 0) g_colsq[i] = v;
        }
    } else {
        // ---- L[i,o,d]: out_plus + out_cat + (t_i+t_j)/2 halves of max/min ----
        int lb = bid - NCOL;
        int i = lb >> 1, o = lb & 1;
        int d = t & 63, g = t >> 6;                    // 12 j-slices
        float sp = 0.f, smx = 0.f, smn = 0.f, sct = 0.f;
        for (int j = g; j < NCOL; j += 12) {
            int ij = ((i * NCOL + j) * 2 + o) * D + d;
            int ji = ((j * NCOL + i) * 2 + o) * D + d;
            sp  += Wops[ij]          + Wops[ji];
            smx += Wops[2 * SZ + ij] + Wops[2 * SZ + ji];
            smn += Wops[3 * SZ + ij] + Wops[3 * SZ + ji];
            sct += Wcat[((i * NCOL + j) * 2 + o) * (2 * D) + d]        // Wc1 row-sum
                 + Wcat[((j * NCOL + i) * 2 + o) * (2 * D) + D + d];   // Wc2 col-sum
        }
        __shared__ float4 s_red[12][64];
        s_red[g][d] = make_float4(sp, smx, smn, sct);
        __syncthreads();
        if (t < 64) {
            float vsp = 0.f, vmx = 0.f, vmn = 0.f, vct = 0.f;
#pragma unroll
            for (int k = 0; k < 12; k++) {
                float4 r = s_red[k][t];
                vsp += r.x; vmx += r.y; vmn += r.z; vct += r.w;
            }
            g_L[lb * D + t] = aw[0] * vsp + aw[4] * vct
                            + 0.5f * (aw[2] * vmx + aw[3] * vmn);
        }
    }
}

// ---------------- k_S: symmetrize weights inline + tabulate per (pair,e1,e2) --
// S[p][e1][e2] = { sum_d wq0*Ti*Tj + wd0*|Ti-Tj| , same with wq1/wd1 }
// Diagonal pairs fold the linear term into e1==e2 entries (only ones read).
__global__ void __launch_bounds__(256, 6)
k_S(const float* __restrict__ Wops, const float* __restrict__ aw) {
    int p = blockIdx.x;
    int i, j; pair_ij(p, i, j);
    int t = threadIdx.x;
    bool diag = (i == j);

    __shared__ float  sTi[NEMB][D + 1];  // +1 pad: e-stride 65 -> distinct banks
    __shared__ float  sTj[NEMB][D + 1];
    __shared__ float  sWraw[12][D];      // 12 raw weight rows
    __shared__ float4 sW[D];             // {wq0,wq1,wd0,wd1}
    __shared__ float  sL[2 * D];

    // T tiles (padded)
    for (int idx = t; idx < NEMB * D; idx += 256) {
        int e = idx >> 6, d = idx & 63;
        sTi[e][d] = g_T[i * NEMB * D + idx];
        sTj[e][d] = g_T[j * NEMB * D + idx];
    }
    // 12 raw weight rows: op in {Wm=1, Wmax=2, Wmin=3} x dir{ij,ji} x o{0,1}
    {
        int rij = (i * NCOL + j) * 2, rji = (j * NCOL + i) * 2;
        for (int idx = t; idx < 12 * D; idx += 256) {
            int r = idx >> 6, d = idx & 63;
            int op = 1 + (r >> 2);              // r/4: 0->Wm,1->Wmax,2->Wmin
            int sub = r & 3;                    // dir*2 + o
            int row = (sub < 2) ? rij : rji;
            int o   = sub & 1;
            sWraw[r][d] = Wops[op * SZ + (row + o) * D + d];
        }
    }
    if (diag)
        for (int idx = t; idx < 2 * D; idx += 256) sL[idx] = g_L[i * 2 * D + idx];
    __syncthreads();

    // symmetrize: 256 threads = 4 components x 64 d
    if (t < 4 * D) {
        int comp = t >> 6, d = t & 63;
        float aw1 = aw[1], aw2 = aw[2], aw3 = aw[3];
        float v;
        if (comp < 2) {          // wq for o = comp
            v = diag ? aw1 * sWraw[comp][d]
                     : aw1 * (sWraw[comp][d] + sWraw[2 + comp][d]);
        } else if (diag) {
            v = 0.f;             // wd vanishes on diagonal
        } else {
            int o = comp - 2;
            v = 0.5f * (aw2 * (sWraw[4 + o][d] + sWraw[6 + o][d])
                      - aw3 * (sWraw[8 + o][d] + sWraw[10 + o][d]));
        }
        float* f = (float*)&sW[d];
        f[comp] = v;
    }
    __syncthreads();

    if (t < NE2) {
        int e1 = t / NEMB, e2 = t % NEMB;
        bool dl = diag && (e1 == e2);
        float s0 = 0.f, s1 = 0.f, l0 = 0.f, l1 = 0.f;
#pragma unroll 4
        for (int d = 0; d < D; d++) {
            float4 w = sW[d];
            float ti = sTi[e1][d], tj = sTj[e2][d];
            float m = ti * tj;
            float a = fabsf(ti - tj);
            s0 = fmaf(w.x, m, fmaf(w.z, a, s0));
            s1 = fmaf(w.y, m, fmaf(w.w, a, s1));
            if (dl) { l0 = fmaf(ti, sL[d], l0); l1 = fmaf(ti, sL[D + d], l1); }
        }
        if (dl) { s0 += l0; s1 += l1; }
        g_S[p * NE2 + t] = make_float2(s0, s1);
    }
}

// ---------------- k_main: batch-per-lane gathers (warp-uniform pair) ---------
// Block: 16 batches, 8 warps. Warp w owns pair chunk [w*32, w*32+32).
// Lane = (subchunk s, batch bl): 16 lanes share one pair -> gather instruction
// touches few S-slabs instead of 32.
__global__ void __launch_bounds__(256, 8)
k_main(const int* __restrict__ features, float* __restrict__ out, int out_size) {
    __shared__ int   s_feat[NCOL][16];
    __shared__ float s_red[8][16][2];
    int t = threadIdx.x;
    int b0 = blockIdx.x * 16;

    for (int idx = t; idx < NCOL * 16; idx += 256)
        s_feat[idx >> 4][idx & 15] = features[(idx >> 4) * B + b0 + (idx & 15)];
    __syncthreads();

    int w = t >> 5, l = t & 31;
    int bl = l & 15, s = l >> 4;
    int pc = w * 32 + s * 16;
    int i, j; pair_ij(pc, i, j);

    float a0 = 0.f, a1 = 0.f;
#pragma unroll
    for (int k = 0; k < 16; k++) {
        int p = pc + k;
        if (p < NPAIR) {
            int e1 = s_feat[i][bl], e2 = s_feat[j][bl];
            float2 v = __ldg(&g_S[p * NE2 + e1 * NEMB + e2]);
            a0 += v.x; a1 += v.y;
            j++; if (j == NCOL) { i++; j = i; }
        }
    }
    a0 += __shfl_xor_sync(0xffffffffu, a0, 16);
    a1 += __shfl_xor_sync(0xffffffffu, a1, 16);
    if (s == 0) { s_red[w][bl][0] = a0; s_red[w][bl][1] = a1; }
    __syncthreads();
    if (t < 16) {
        float r0 = 0.f, r1 = 0.f;
#pragma unroll
        for (int ww = 0; ww < 8; ww++) { r0 += s_red[ww][t][0]; r1 += s_red[ww][t][1]; }
        int b = b0 + t;
        out[b * 2] = r0; out[b * 2 + 1] = r1;
    }

    // regularizer scalar (colsq ready from k_pre)
    if (blockIdx.x == 0 && t >= 32 && t < 64 && out_size > 2 * B) {
        int ll = t - 32;
        float v = (ll < NCOL) ? sqrtf(g_colsq[ll]) : 0.f;
#pragma unroll
        for (int o = 16; o; o >>= 1) v += __shfl_xor_sync(0xffffffffu, v, o);
        if (ll == 0) out[2 * B] = 0.001f * (2.0f * NCOL) * v;
    }
}

// ---------------- launch -----------------------------------------------------
extern "C" void kernel_launch(void* const* d_in, const int* in_sizes, int n_in,
                              void* d_out, int out_size) {
    const int*   features = (const int*)  d_in[0];
    const float* tables   = (const float*)d_in[1];
    const float* w1       = (const float*)d_in[2];
    const float* b1       = (const float*)d_in[3];
    const float* w2       = (const float*)d_in[4];
    const float* b2       = (const float*)d_in[5];
    const float* Wops     = (const float*)d_in[6];
    const float* Wcat     = (const float*)d_in[7];
    const float* aw       = (const float*)d_in[8];
    float* out = (float*)d_out;

    k_pre  <<<NCOL * 3, 768>>>(tables, features, w1, b1, w2, b2, Wops, Wcat, aw);
    k_S    <<<NPAIR, 256>>>(Wops, aw);
    k_main <<<B / 16, 256>>>(features, out, out_size);
}

// round 10
// speedup vs baseline: 1.2885x; 1.0117x over previous
#include <cuda_runtime.h>
#include <math.h>

#define NCOL 22
#define NEMB 12
#define D    64
#define B    2048
#define NPAIR 253           // 22 diag + 231 upper pairs
#define NE2  (NEMB*NEMB)    // 144
#define SZ   (NCOL*NCOL*2*D)

// ---------------- scratch (device globals; no allocation allowed) ------------
__device__ float  g_T[NCOL * NEMB * D];        // f(tables), 66 KB
__device__ float  g_n2[NCOL * NEMB];           // per-(col,e) squared norms
__device__ float  g_colsq[NCOL];               // per-col sum over batch
__device__ float  g_L[NCOL * 2 * D];           // folded linear weights [i][o][d]
__device__ float2 g_S[NPAIR * NE2];            // pairwise lookup table, 291 KB

// p -> (i,j) upper-triangular-incl-diag enumeration
__device__ __forceinline__ void pair_ij(int p, int& i, int& j) {
    int ii = 0, rem = p;
    while (rem >= NCOL - ii) { rem -= NCOL - ii; ii++; }
    i = ii; j = ii + rem;
}

// fast tanh: EX2 + RCP, safe for any x
__device__ __forceinline__ float tanh_fast(float x) {
    float e = __expf(-2.0f * fabsf(x));
    float t = __fdividef(1.0f - e, 1.0f + e);
    return copysignf(t, x);
}

// ---------------- k_pre: embed (blocks 0..65) + folded linear L (66..109) ----
// embed: 3 blocks per column, 4 e-rows each -> one shallow load->tanh->store chain
// L: one block per (i,o), 4 j-slices, loop unrolled for front-batched loads
__global__ void __launch_bounds__(256, 6)
k_pre(const float* __restrict__ tables,
      const float* __restrict__ w1, const float* __restrict__ b1,
      const float* __restrict__ w2, const float* __restrict__ b2,
      const float* __restrict__ Wops, const float* __restrict__ Wcat,
      const float* __restrict__ aw) {
    int bid = blockIdx.x, t = threadIdx.x;

    if (bid < 3 * NCOL) {
        // ---- embed chunk: column i, e-rows [c*4, c*4+4) ----
        int i = bid / 3, c = bid % 3;
        int idx = c * 256 + t;
        float x = tables[i * NEMB * D + idx];
        float acc = b2[0];
#pragma unroll
        for (int h = 0; h < 8; h++) acc += w2[h] * tanh_fast(x * w1[h] + b1[h]);
        g_T[i * NEMB * D + idx] = acc;

        // n2 per e-row: each warp = half a row; 8 warp partials -> 4 rows
        float sq = x * x;
#pragma unroll
        for (int o = 16; o; o >>= 1) sq += __shfl_xor_sync(0xffffffffu, sq, o);
        __shared__ float s_warp[8];
        if ((t & 31) == 0) s_warp[t >> 5] = sq;
        __syncthreads();
        if (t < 4) g_n2[i * NEMB + c * 4 + t] = s_warp[2 * t] + s_warp[2 * t + 1];
    } else {
        // ---- L[i,o,d]: out_plus + out_cat + (t_i+t_j)/2 halves of max/min ----
        int lb = bid - 3 * NCOL;
        int i = lb >> 1, o = lb & 1;
        int d = t & 63, g = t >> 6;                    // 4 j-slices
        float sp = 0.f, smx = 0.f, smn = 0.f, sct = 0.f;
#pragma unroll
        for (int jj = 0; jj < 6; jj++) {
            int j = g + jj * 4;
            if (j < NCOL) {
                int ij = ((i * NCOL + j) * 2 + o) * D + d;
                int ji = ((j * NCOL + i) * 2 + o) * D + d;
                sp  += Wops[ij]          + Wops[ji];
                smx += Wops[2 * SZ + ij] + Wops[2 * SZ + ji];
                smn += Wops[3 * SZ + ij] + Wops[3 * SZ + ji];
                sct += Wcat[((i * NCOL + j) * 2 + o) * (2 * D) + d]        // Wc1 row-sum
                     + Wcat[((j * NCOL + i) * 2 + o) * (2 * D) + D + d];   // Wc2 col-sum
            }
        }
        __shared__ float4 s_red[4][64];
        s_red[g][d] = make_float4(sp, smx, smn, sct);
        __syncthreads();
        if (t < 64) {
            float4 a = s_red[0][t], b = s_red[1][t], c = s_red[2][t], e = s_red[3][t];
            g_L[lb * D + t] = aw[0] * (a.x + b.x + c.x + e.x)
                            + aw[4] * (a.w + b.w + c.w + e.w)
                            + 0.5f * (aw[2] * (a.y + b.y + c.y + e.y)
                                    + aw[3] * (a.z + b.z + c.z + e.z));
        }
    }
}

// ---------------- k_S: pair tabulation (0..252) + colsq gather (253..274) ----
// S[p][e1][e2] = { sum_d wq0*Ti*Tj + wd0*|Ti-Tj| , same with wq1/wd1 }
// Diagonal pairs fold the linear term into e1==e2 entries (only ones read).
// colsq blocks overlap with pair blocks (depend only on g_n2 from k_pre).
__global__ void __launch_bounds__(256, 6)
k_S(const float* __restrict__ Wops, const float* __restrict__ aw,
    const int* __restrict__ features) {
    int bid = blockIdx.x, t = threadIdx.x;

    if (bid >= NPAIR) {
        // ---- colsq[i] = sum_b n2[i, feat[i,b]] ----
        int i = bid - NPAIR;
        __shared__ float s_n2c[NEMB];
        __shared__ float s_w[8];
        if (t < NEMB) s_n2c[t] = g_n2[i * NEMB + t];
        __syncthreads();
        float sum = 0.f;
        for (int b = t; b < B; b += 256)
            sum += s_n2c[features[i * B + b]];
#pragma unroll
        for (int o = 16; o; o >>= 1) sum += __shfl_xor_sync(0xffffffffu, sum, o);
        if ((t & 31) == 0) s_w[t >> 5] = sum;
        __syncthreads();
        if (t == 0) {
            float v = 0.f;
            for (int k = 0; k < 8; k++) v += s_w[k];
            g_colsq[i] = v;
        }
        return;
    }

    int p = bid;
    int i, j; pair_ij(p, i, j);
    bool diag = (i == j);

    __shared__ float  sTi[NEMB][D + 1];  // +1 pad: e-stride 65 -> distinct banks
    __shared__ float  sTj[NEMB][D + 1];
    __shared__ float  sWraw[12][D];      // 12 raw weight rows
    __shared__ float4 sW[D];             // {wq0,wq1,wd0,wd1}
    __shared__ float  sL[2 * D];

    for (int idx = t; idx < NEMB * D; idx += 256) {
        int e = idx >> 6, d = idx & 63;
        sTi[e][d] = g_T[i * NEMB * D + idx];
        sTj[e][d] = g_T[j * NEMB * D + idx];
    }
    // 12 raw weight rows: op in {Wm=1, Wmax=2, Wmin=3} x dir{ij,ji} x o{0,1}
    {
        int rij = (i * NCOL + j) * 2, rji = (j * NCOL + i) * 2;
        for (int idx = t; idx < 12 * D; idx += 256) {
            int r = idx >> 6, d = idx & 63;
            int op = 1 + (r >> 2);              // r/4: 0->Wm,1->Wmax,2->Wmin
            int sub = r & 3;                    // dir*2 + o
            int row = (sub < 2) ? rij : rji;
            int o   = sub & 1;
            sWraw[r][d] = Wops[op * SZ + (row + o) * D + d];
        }
    }
    if (diag)
        for (int idx = t; idx < 2 * D; idx += 256) sL[idx] = g_L[i * 2 * D + idx];
    __syncthreads();

    // symmetrize: 256 threads = 4 components x 64 d
    if (t < 4 * D) {
        int comp = t >> 6, d = t & 63;
        float aw1 = aw[1], aw2 = aw[2], aw3 = aw[3];
        float v;
        if (comp < 2) {          // wq for o = comp
            v = diag ? aw1 * sWraw[comp][d]
                     : aw1 * (sWraw[comp][d] + sWraw[2 + comp][d]);
        } else if (diag) {
            v = 0.f;             // wd vanishes on diagonal
        } else {
            int o = comp - 2;
            v = 0.5f * (aw2 * (sWraw[4 + o][d] + sWraw[6 + o][d])
                      - aw3 * (sWraw[8 + o][d] + sWraw[10 + o][d]));
        }
        float* f = (float*)&sW[d];
        f[comp] = v;
    }
    __syncthreads();

    if (t < NE2) {
        int e1 = t / NEMB, e2 = t % NEMB;
        bool dl = diag && (e1 == e2);
        float s0 = 0.f, s1 = 0.f, l0 = 0.f, l1 = 0.f;
#pragma unroll 4
        for (int d = 0; d < D; d++) {
            float4 w = sW[d];
            float ti = sTi[e1][d], tj = sTj[e2][d];
            float m = ti * tj;
            float a = fabsf(ti - tj);
            s0 = fmaf(w.x, m, fmaf(w.z, a, s0));
            s1 = fmaf(w.y, m, fmaf(w.w, a, s1));
            if (dl) { l0 = fmaf(ti, sL[d], l0); l1 = fmaf(ti, sL[D + d], l1); }
        }
        if (dl) { s0 += l0; s1 += l1; }
        g_S[p * NE2 + t] = make_float2(s0, s1);
    }
}

// ---------------- k_main: batch-per-lane gathers (warp-uniform pair) ---------
__global__ void __launch_bounds__(256, 8)
k_main(const int* __restrict__ features, float* __restrict__ out, int out_size) {
    __shared__ int   s_feat[NCOL][16];
    __shared__ float s_red[8][16][2];
    int t = threadIdx.x;
    int b0 = blockIdx.x * 16;

    for (int idx = t; idx < NCOL * 16; idx += 256)
        s_feat[idx >> 4][idx & 15] = features[(idx >> 4) * B + b0 + (idx & 15)];
    __syncthreads();

    int w = t >> 5, l = t & 31;
    int bl = l & 15, s = l >> 4;
    int pc = w * 32 + s * 16;
    int i, j; pair_ij(pc, i, j);

    float a0 = 0.f, a1 = 0.f;
#pragma unroll
    for (int k = 0; k < 16; k++) {
        int p = pc + k;
        if (p < NPAIR) {
            int e1 = s_feat[i][bl], e2 = s_feat[j][bl];
            float2 v = __ldg(&g_S[p * NE2 + e1 * NEMB + e2]);
            a0 += v.x; a1 += v.y;
            j++; if (j == NCOL) { i++; j = i; }
        }
    }
    a0 += __shfl_xor_sync(0xffffffffu, a0, 16);
    a1 += __shfl_xor_sync(0xffffffffu, a1, 16);
    if (s == 0) { s_red[w][bl][0] = a0; s_red[w][bl][1] = a1; }
    __syncthreads();
    if (t < 16) {
        float r0 = 0.f, r1 = 0.f;
#pragma unroll
        for (int ww = 0; ww < 8; ww++) { r0 += s_red[ww][t][0]; r1 += s_red[ww][t][1]; }
        int b = b0 + t;
        out[b * 2] = r0; out[b * 2 + 1] = r1;
    }

    // regularizer scalar (colsq ready from k_S)
    if (blockIdx.x == 0 && t >= 32 && t < 64 && out_size > 2 * B) {
        int ll = t - 32;
        float v = (ll < NCOL) ? sqrtf(g_colsq[ll]) : 0.f;
#pragma unroll
        for (int o = 16; o; o >>= 1) v += __shfl_xor_sync(0xffffffffu, v, o);
        if (ll == 0) out[2 * B] = 0.001f * (2.0f * NCOL) * v;
    }
}

// ---------------- launch -----------------------------------------------------
extern "C" void kernel_launch(void* const* d_in, const int* in_sizes, int n_in,
                              void* d_out, int out_size) {
    const int*   features = (const int*)  d_in[0];
    const float* tables   = (const float*)d_in[1];
    const float* w1       = (const float*)d_in[2];
    const float* b1       = (const float*)d_in[3];
    const float* w2       = (const float*)d_in[4];
    const float* b2       = (const float*)d_in[5];
    const float* Wops     = (const float*)d_in[6];
    const float* Wcat     = (const float*)d_in[7];
    const float* aw       = (const float*)d_in[8];
    float* out = (float*)d_out;

    k_pre  <<<3 * NCOL + 2 * NCOL, 256>>>(tables, w1, b1, w2, b2, Wops, Wcat, aw);
    k_S    <<<NPAIR + NCOL, 256>>>(Wops, aw, features);
    k_main <<<B / 16, 256>>>(features, out, out_size);
}

// round 11
// speedup vs baseline: 1.4722x; 1.1425x over previous
#include <cuda_runtime.h>
#include <math.h>

#define NCOL 22
#define NEMB 12
#define D    64
#define B    2048
#define NPAIR 253           // 22 diag + 231 upper pairs
#define NE2  (NEMB*NEMB)    // 144
#define SZ   (NCOL*NCOL*2*D)

// ---------------- scratch (device globals; no allocation allowed) ------------
__device__ float  g_T[NCOL * NEMB * D];        // f(tables), 66 KB
__device__ float  g_n2[NCOL * NEMB];           // per-(col,e) squared norms
__device__ float  g_colsq[NCOL];               // per-col sum over batch
__device__ float  g_L[NCOL * 2 * D];           // folded linear weights [i][o][d]
__device__ float2 g_S[NPAIR * NE2];            // pairwise lookup table, 291 KB

// p -> (i,j) upper-triangular-incl-diag enumeration
__device__ __forceinline__ void pair_ij(int p, int& i, int& j) {
    int ii = 0, rem = p;
    while (rem >= NCOL - ii) { rem -= NCOL - ii; ii++; }
    i = ii; j = ii + rem;
}

// fast tanh: EX2 + RCP, safe for any x
__device__ __forceinline__ float tanh_fast(float x) {
    float e = __expf(-2.0f * fabsf(x));
    float t = __fdividef(1.0f - e, 1.0f + e);
    return copysignf(t, x);
}

// ---------------- k_pre: embed (blocks 0..32) + folded linear L (33..76) -----
// 512 threads, NO occupancy cap: registers free for load front-batching.
// embed: flat 33x512 over 22*12*64 table elements, one load->tanh->store chain.
// L: 8 j-slices -> 18 front-batched loads/thread, 1-2 DRAM rounds.
__global__ void __launch_bounds__(512)
k_pre(const float* __restrict__ tables,
      const float* __restrict__ w1, const float* __restrict__ b1,
      const float* __restrict__ w2, const float* __restrict__ b2,
      const float* __restrict__ Wops, const float* __restrict__ Wcat,
      const float* __restrict__ aw) {
    int bid = blockIdx.x, t = threadIdx.x;

    if (bid < 33) {
        // ---- embed: flat chunk of 512 table elements (8 e-rows) ----
        int idx = bid * 512 + t;                       // < 16896
        float x = tables[idx];
        float acc = b2[0];
#pragma unroll
        for (int h = 0; h < 8; h++) acc += w2[h] * tanh_fast(x * w1[h] + b1[h]);
        g_T[idx] = acc;

        // n2 per e-row (64 elems = 2 warps)
        float sq = x * x;
#pragma unroll
        for (int o = 16; o; o >>= 1) sq += __shfl_xor_sync(0xffffffffu, sq, o);
        __shared__ float s_warp[16];
        if ((t & 31) == 0) s_warp[t >> 5] = sq;
        __syncthreads();
        if (t < 8) g_n2[bid * 8 + t] = s_warp[2 * t] + s_warp[2 * t + 1];
    } else {
        // ---- L[i,o,d]: out_plus + out_cat + (t_i+t_j)/2 halves of max/min ----
        int lb = bid - 33;
        int i = lb >> 1, o = lb & 1;
        int d = t & 63, g = t >> 6;                    // 8 j-slices
        float sp = 0.f, smx = 0.f, smn = 0.f, sct = 0.f;
#pragma unroll
        for (int jj = 0; jj < 3; jj++) {
            int j = g + jj * 8;
            if (j < NCOL) {
                int ij = ((i * NCOL + j) * 2 + o) * D + d;
                int ji = ((j * NCOL + i) * 2 + o) * D + d;
                sp  += Wops[ij]          + Wops[ji];
                smx += Wops[2 * SZ + ij] + Wops[2 * SZ + ji];
                smn += Wops[3 * SZ + ij] + Wops[3 * SZ + ji];
                sct += Wcat[((i * NCOL + j) * 2 + o) * (2 * D) + d]        // Wc1 row-sum
                     + Wcat[((j * NCOL + i) * 2 + o) * (2 * D) + D + d];   // Wc2 col-sum
            }
        }
        __shared__ float4 s_red[8][64];
        s_red[g][d] = make_float4(sp, smx, smn, sct);
        __syncthreads();
        if (t < 64) {
            float vsp = 0.f, vmx = 0.f, vmn = 0.f, vct = 0.f;
#pragma unroll
            for (int k = 0; k < 8; k++) {
                float4 r = s_red[k][t];
                vsp += r.x; vmx += r.y; vmn += r.z; vct += r.w;
            }
            g_L[lb * D + t] = aw[0] * vsp + aw[4] * vct
                            + 0.5f * (aw[2] * vmx + aw[3] * vmn);
        }
    }
}

// ---------------- k_S: pair tabulation (0..252) + colsq gather (253..274) ----
__global__ void __launch_bounds__(256, 6)
k_S(const float* __restrict__ Wops, const float* __restrict__ aw,
    const int* __restrict__ features) {
    int bid = blockIdx.x, t = threadIdx.x;

    if (bid >= NPAIR) {
        // ---- colsq[i] = sum_b n2[i, feat[i,b]] (overlaps with pair blocks) ----
        int i = bid - NPAIR;
        __shared__ float s_n2c[NEMB];
        __shared__ float s_w[8];
        if (t < NEMB) s_n2c[t] = g_n2[i * NEMB + t];
        __syncthreads();
        float sum = 0.f;
        for (int b = t; b < B; b += 256)
            sum += s_n2c[features[i * B + b]];
#pragma unroll
        for (int o = 16; o; o >>= 1) sum += __shfl_xor_sync(0xffffffffu, sum, o);
        if ((t & 31) == 0) s_w[t >> 5] = sum;
        __syncthreads();
        if (t == 0) {
            float v = 0.f;
            for (int k = 0; k < 8; k++) v += s_w[k];
            g_colsq[i] = v;
        }
        return;
    }

    int p = bid;
    int i, j; pair_ij(p, i, j);
    bool diag = (i == j);

    __shared__ float  sTi[NEMB][D + 1];  // +1 pad: e-stride 65 -> distinct banks
    __shared__ float  sTj[NEMB][D + 1];
    __shared__ float  sWraw[12][D];      // 12 raw weight rows
    __shared__ float4 sW[D];             // {wq0,wq1,wd0,wd1}
    __shared__ float  sL[2 * D];

    for (int idx = t; idx < NEMB * D; idx += 256) {
        int e = idx >> 6, d = idx & 63;
        sTi[e][d] = g_T[i * NEMB * D + idx];
        sTj[e][d] = g_T[j * NEMB * D + idx];
    }
    // 12 raw weight rows: op in {Wm=1, Wmax=2, Wmin=3} x dir{ij,ji} x o{0,1}
    {
        int rij = (i * NCOL + j) * 2, rji = (j * NCOL + i) * 2;
        for (int idx = t; idx < 12 * D; idx += 256) {
            int r = idx >> 6, d = idx & 63;
            int op = 1 + (r >> 2);              // r/4: 0->Wm,1->Wmax,2->Wmin
            int sub = r & 3;                    // dir*2 + o
            int row = (sub < 2) ? rij : rji;
            int o   = sub & 1;
            sWraw[r][d] = Wops[op * SZ + (row + o) * D + d];
        }
    }
    if (diag)
        for (int idx = t; idx < 2 * D; idx += 256) sL[idx] = g_L[i * 2 * D + idx];
    __syncthreads();

    // symmetrize: 256 threads = 4 components x 64 d
    if (t < 4 * D) {
        int comp = t >> 6, d = t & 63;
        float aw1 = aw[1], aw2 = aw[2], aw3 = aw[3];
        float v;
        if (comp < 2) {          // wq for o = comp
            v = diag ? aw1 * sWraw[comp][d]
                     : aw1 * (sWraw[comp][d] + sWraw[2 + comp][d]);
        } else if (diag) {
            v = 0.f;             // wd vanishes on diagonal
        } else {
            int o = comp - 2;
            v = 0.5f * (aw2 * (sWraw[4 + o][d] + sWraw[6 + o][d])
                      - aw3 * (sWraw[8 + o][d] + sWraw[10 + o][d]));
        }
        float* f = (float*)&sW[d];
        f[comp] = v;
    }
    __syncthreads();

    if (t < NE2) {
        int e1 = t / NEMB, e2 = t % NEMB;
        bool dl = diag && (e1 == e2);
        float s0 = 0.f, s1 = 0.f, l0 = 0.f, l1 = 0.f;
#pragma unroll 4
        for (int d = 0; d < D; d++) {
            float4 w = sW[d];
            float ti = sTi[e1][d], tj = sTj[e2][d];
            float m = ti * tj;
            float a = fabsf(ti - tj);
            s0 = fmaf(w.x, m, fmaf(w.z, a, s0));
            s1 = fmaf(w.y, m, fmaf(w.w, a, s1));
            if (dl) { l0 = fmaf(ti, sL[d], l0); l1 = fmaf(ti, sL[D + d], l1); }
        }
        if (dl) { s0 += l0; s1 += l1; }
        g_S[p * NE2 + t] = make_float2(s0, s1);
    }
}

// ---------------- k_main: 256 blocks, 8 batches each, 8 gathers/lane ---------
// Warp w owns pair chunk [w*32, (w+1)*32). Lane = (s in 0..3, bl in 0..7):
// subchunk s covers 8 pairs; reduce over s via shfl_xor(8,16).
__global__ void __launch_bounds__(256, 8)
k_main(const int* __restrict__ features, float* __restrict__ out, int out_size) {
    __shared__ int   s_feat[NCOL][8];
    __shared__ float s_red[8][8][2];
    int t = threadIdx.x;
    int b0 = blockIdx.x * 8;

    for (int idx = t; idx < NCOL * 8; idx += 256)
        s_feat[idx >> 3][idx & 7] = features[(idx >> 3) * B + b0 + (idx & 7)];
    __syncthreads();

    int w = t >> 5, l = t & 31;
    int bl = l & 7, s = l >> 3;        // 4 subchunks of 8 pairs
    int pc = w * 32 + s * 8;
    int i, j; pair_ij(pc, i, j);

    float a0 = 0.f, a1 = 0.f;
#pragma unroll
    for (int k = 0; k < 8; k++) {
        int p = pc + k;
        if (p < NPAIR) {
            int e1 = s_feat[i][bl], e2 = s_feat[j][bl];
            float2 v = __ldg(&g_S[p * NE2 + e1 * NEMB + e2]);
            a0 += v.x; a1 += v.y;
            j++; if (j == NCOL) { i++; j = i; }
        }
    }
    a0 += __shfl_xor_sync(0xffffffffu, a0, 8);
    a1 += __shfl_xor_sync(0xffffffffu, a1, 8);
    a0 += __shfl_xor_sync(0xffffffffu, a0, 16);
    a1 += __shfl_xor_sync(0xffffffffu, a1, 16);
    if (s == 0) { s_red[w][bl][0] = a0; s_red[w][bl][1] = a1; }
    __syncthreads();
    if (t < 8) {
        float r0 = 0.f, r1 = 0.f;
#pragma unroll
        for (int ww = 0; ww < 8; ww++) { r0 += s_red[ww][t][0]; r1 += s_red[ww][t][1]; }
        int b = b0 + t;
        out[b * 2] = r0; out[b * 2 + 1] = r1;
    }

    // regularizer scalar (colsq ready from k_S)
    if (blockIdx.x == 0 && t >= 32 && t < 64 && out_size > 2 * B) {
        int ll = t - 32;
        float v = (ll < NCOL) ? sqrtf(g_colsq[ll]) : 0.f;
#pragma unroll
        for (int o = 16; o; o >>= 1) v += __shfl_xor_sync(0xffffffffu, v, o);
        if (ll == 0) out[2 * B] = 0.001f * (2.0f * NCOL) * v;
    }
}

// ---------------- launch -----------------------------------------------------
extern "C" void kernel_launch(void* const* d_in, const int* in_sizes, int n_in,
                              void* d_out, int out_size) {
    const int*   features = (const int*)  d_in[0];
    const float* tables   = (const float*)d_in[1];
    const float* w1       = (const float*)d_in[2];
    const float* b1       = (const float*)d_in[3];
    const float* w2       = (const float*)d_in[4];
    const float* b2       = (const float*)d_in[5];
    const float* Wops     = (const float*)d_in[6];
    const float* Wcat     = (const float*)d_in[7];
    const float* aw       = (const float*)d_in[8];
    float* out = (float*)d_out;

    k_pre  <<<33 + 2 * NCOL, 512>>>(tables, w1, b1, w2, b2, Wops, Wcat, aw);
    k_S    <<<NPAIR + NCOL, 256>>>(Wops, aw, features);
    k_main <<<B / 8, 256>>>(features, out, out_size);
}